// round 4
// baseline (speedup 1.0000x reference)
#include <cuda_runtime.h>
#include <math.h>
#include <stdint.h>

#ifndef M_PI
#define M_PI 3.14159265358979323846
#endif

// ---------------- problem constants ----------------
#define PB   8      // B
#define PUP  8      // UP
#define PA   32     // A
#define PL   3264   // L
#define PH   256    // H
#define PBSZ 12
#define PK   12
#define LOCC 4
#define LON  816    // L/LOCC
#define NB   272    // L/BSZ
#define NOFF 61     // DMAX-DMIN+1
#define DMIN (-30)
#define R1   51     // L = 51*64
#define U1   64
#define NROW (PB*PUP)     // 64
#define FEATK (2*PL)      // 6528
#define KSPL 16           // k-splits for gemm1
#define KRNG (FEATK/KSPL) // 408

// ---------------- device scratch (static, no allocs) ----------------
__device__ float2 d_tw[PL];                       // e^{+2pi i r/L}
__device__ float2 d_Y[PB*PA*U1*R1];               // [(b*A+a)*64+u]*51+r
__device__ float  d_m[NROW], d_toff[NROW];
__device__ float2 d_phm[NROW*PL], d_phT[NROW*PL];
__device__ float2 d_havg[NROW*PA*LON];
__device__ float2 d_res[PB*PA*PL];
__device__ float  d_feat[NROW*FEATK];
__device__ float  d_h1p[KSPL*NROW*PH];
__device__ float  d_h1[NROW*PH];
__device__ float  d_o2[NROW*576];
__device__ float2 d_wm[NROW*PBSZ*PBSZ];

// ---------------- helpers ----------------
__device__ __forceinline__ float2 cmul(float2 a, float2 b) {
    return make_float2(a.x*b.x - a.y*b.y, a.x*b.y + a.y*b.x);
}
__device__ __forceinline__ float2 cmulc(float2 a, float2 b) { // a * conj(b)
    return make_float2(a.x*b.x + a.y*b.y, a.y*b.x - a.x*b.y);
}
// jnp.interp replica on a LON-length table (xp = 1.5 + 4j)
__device__ __forceinline__ float2 lerp_havg(const float2* hv, int n) {
    float t = ((float)n - 1.5f) * 0.25f;
    if (t <= 0.f) return hv[0];
    if (t >= (float)(LON-1)) return hv[LON-1];
    int j = (int)t;
    float f = t - (float)j;
    float2 a = hv[j], b = hv[j+1];
    return make_float2(a.x + (b.x-a.x)*f, a.y + (b.y-a.y)*f);
}

// ---------------- K0: twiddles ----------------
__global__ void k_tw() {
    int i = blockIdx.x*blockDim.x + threadIdx.x;
    if (i < PL) {
        double a = 2.0*M_PI*(double)i/(double)PL;
        d_tw[i] = make_float2((float)cos(a), (float)sin(a));
    }
}

// ---------------- K1: partial-DFT stage 1 ----------------
// Y[r,u] = sum_q x[51q+r] e^{2pi i q u /64}, split q = 8q1+q0
__global__ void k_stage1(const float* __restrict__ lr, const float* __restrict__ li) {
    __shared__ float2 z[R1*64];      // Z[(r*8+q0)*8+v]
    __shared__ float2 t64[64];
    int ba = blockIdx.x;
    const float* rr = lr + (size_t)ba*PL;
    const float* ri = li + (size_t)ba*PL;
    for (int k = threadIdx.x; k < 64; k += blockDim.x) t64[k] = d_tw[k*R1];
    __syncthreads();
    // stage A: 8-point DFT over q1
    for (int o = threadIdx.x; o < R1*64; o += blockDim.x) {
        int v = o & 7, q0 = (o>>3)&7, r = o>>6;
        float2 acc = make_float2(0.f,0.f);
        #pragma unroll
        for (int q1 = 0; q1 < 8; q1++) {
            int id = 51*(8*q1+q0)+r;
            float2 xv = make_float2(rr[id], ri[id]);
            float2 w = t64[8*((q1*v)&7)];
            acc.x += xv.x*w.x - xv.y*w.y;
            acc.y += xv.x*w.y + xv.y*w.x;
        }
        z[(r*8+q0)*8+v] = acc;
    }
    __syncthreads();
    // stage B: combine over q0
    for (int o = threadIdx.x; o < R1*64; o += blockDim.x) {
        int u = o & 63, r = o >> 6, v = u & 7;
        float2 acc = make_float2(0.f,0.f);
        #pragma unroll
        for (int q0 = 0; q0 < 8; q0++) {
            float2 w = t64[(q0*u)&63];
            float2 zv = z[(r*8+q0)*8 + v];
            acc.x += zv.x*w.x - zv.y*w.y;
            acc.y += zv.x*w.y + zv.y*w.x;
        }
        d_Y[((size_t)ba*U1 + u)*R1 + r] = acc;
    }
}

// ---------------- K2: windowed power + argmax -> toff, m ----------------
// Deterministic: one warp per window bin, lane == antenna, fixed-order
// butterfly reduction (no float atomics anywhere in the value path).
__global__ void k_peak(const int* __restrict__ shifts) {
    __shared__ float spow[NOFF];
    int b = blockIdx.x / PUP, up = blockIdx.x % PUP;
    int s = shifts[up];
    int peak = ((PK - s) % PK) * (PL / PK);
    int warp = threadIdx.x >> 5;      // 0..7
    int lane = threadIdx.x & 31;      // antenna index
    for (int d = warp; d < NOFF; d += 8) {
        int t = peak + (DMIN + d);
        t %= PL; if (t < 0) t += PL;
        int u = t & 63;
        const float2* Yp = d_Y + (((size_t)(b*PA+lane))*U1 + u)*R1;
        float2 acc = make_float2(0.f,0.f);
        int idx = 0;
        for (int r = 0; r < R1; r++) {
            float2 w = d_tw[idx];
            float2 y = Yp[r];
            acc.x += y.x*w.x - y.y*w.y;
            acc.y += y.x*w.y + y.y*w.x;
            idx += t; if (idx >= PL) idx -= PL;
        }
        float pw = acc.x*acc.x + acc.y*acc.y;
        #pragma unroll
        for (int off = 16; off > 0; off >>= 1)
            pw += __shfl_xor_sync(0xffffffffu, pw, off);
        if (lane == 0) spow[d] = pw;
    }
    __syncthreads();
    if (threadIdx.x == 0) {
        float vm = spow[0]; int am = 0;
        for (int i = 1; i < NOFF; i++) if (spow[i] > vm) { vm = spow[i]; am = i; }
        float toff = (float)(DMIN + am);
        d_toff[blockIdx.x] = toff;
        d_m[blockIdx.x] = toff + (float)peak;
    }
}

// ---------------- K3: phasor tables (replicate fp32 order of reference) --
__global__ void k_phasor() {
    int bu = blockIdx.x;
    const float w = (float)(2.0 * M_PI / (double)PL);
    float wm = w * d_m[bu];
    float wt = w * d_toff[bu];
    for (int n = threadIdx.x; n < PL; n += blockDim.x) {
        float fn = (float)n;
        float am = wm * fn, at = wt * fn;
        float sm_, cm_; sincosf(am, &sm_, &cm_);
        float st_, ct_; sincosf(at, &st_, &ct_);
        d_phm[(size_t)bu*PL+n] = make_float2(cm_, sm_);
        d_phT[(size_t)bu*PL+n] = make_float2(ct_, st_);
    }
}

// ---------------- K4: h_avg = blockmean(ls * phasor_m) ----------------
__global__ void k_havg(const float* __restrict__ lr, const float* __restrict__ li) {
    int idx = blockIdx.x*blockDim.x + threadIdx.x;
    if (idx >= NROW*PA*LON) return;
    int j = idx % LON; int a = (idx / LON) % PA; int bu = idx / (LON*PA);
    int b = bu / PUP;
    const float* rr = lr + (size_t)(b*PA+a)*PL + 4*j;
    const float* ii = li + (size_t)(b*PA+a)*PL + 4*j;
    const float2* ph = d_phm + (size_t)bu*PL + 4*j;
    float2 acc = make_float2(0.f,0.f);
    #pragma unroll
    for (int c = 0; c < 4; c++) {
        float xr = rr[c], xi = ii[c]; float2 p = ph[c];
        acc.x += xr*p.x - xi*p.y;
        acc.y += xr*p.y + xi*p.x;
    }
    d_havg[idx] = make_float2(acc.x*0.25f, acc.y*0.25f);
}

// ---------------- K5: residual = ls - sum_up interp(h_avg)*conj(phm) ----
__global__ void k_resid(const float* __restrict__ lr, const float* __restrict__ li) {
    int idx = blockIdx.x*blockDim.x + threadIdx.x;
    if (idx >= PB*PA*PL) return;
    int n = idx % PL; int a = (idx/PL) % PA; int b = idx/(PL*PA);
    float2 acc = make_float2(0.f,0.f);
    #pragma unroll 1
    for (int up = 0; up < PUP; up++) {
        int bu = b*PUP+up;
        const float2* hv = d_havg + (size_t)(bu*PA+a)*LON;
        float2 h = lerp_havg(hv, n);
        float2 p = d_phm[(size_t)bu*PL+n];
        float2 c = cmulc(h, p);
        acc.x += c.x; acc.y += c.y;
    }
    d_res[idx] = make_float2(lr[idx]-acc.x, li[idx]-acc.y);
}

// ---------------- K6: energies + antenna argmax + MLP features (fused) --
// One block per (b,up). 32 warps, warp == antenna. Deterministic
// fixed-order butterfly reduction per warp; argmax by thread 0.
__global__ void k_energyfeat() {
    __shared__ float sen[PA];
    __shared__ int s_a;
    int bu = blockIdx.x; int b = bu/PUP;
    int warp = threadIdx.x >> 5;   // antenna
    int lane = threadIdx.x & 31;
    {
        const float2* hv = d_havg + (size_t)(bu*PA+warp)*LON;
        const float2* rs = d_res + (size_t)(b*PA+warp)*PL;
        const float2* ph = d_phm + (size_t)bu*PL;
        float acc = 0.f;
        for (int n = lane; n < PL; n += 32) {
            float2 h = lerp_havg(hv, n);
            float2 r = rs[n]; float2 p = ph[n];
            float hr = h.x + r.x*p.x - r.y*p.y;
            float hi = h.y + r.x*p.y + r.y*p.x;
            acc += hr*hr + hi*hi;
        }
        #pragma unroll
        for (int off = 16; off > 0; off >>= 1)
            acc += __shfl_xor_sync(0xffffffffu, acc, off);
        if (lane == 0) sen[warp] = acc;
    }
    __syncthreads();
    if (threadIdx.x == 0) {
        float vm = sen[0]; int am = 0;
        for (int i = 1; i < PA; i++) if (sen[i] > vm) { vm = sen[i]; am = i; }
        s_a = am;
    }
    __syncthreads();
    int a = s_a;
    const float2* hv = d_havg + (size_t)(bu*PA+a)*LON;
    const float2* rs = d_res + (size_t)(b*PA+a)*PL;
    const float2* ph = d_phm + (size_t)bu*PL;
    for (int n = threadIdx.x; n < PL; n += blockDim.x) {
        float2 h = lerp_havg(hv, n);
        float2 r = rs[n]; float2 p = ph[n];
        float hr = h.x + r.x*p.x - r.y*p.y;
        float hi = h.y + r.x*p.y + r.y*p.x;
        d_feat[(size_t)bu*FEATK + n]      = hr;
        d_feat[(size_t)bu*FEATK + PL + n] = hi;
    }
}

// ---------------- K8: feat @ W1, split-K deterministic partials ----------
__global__ void k_gemm1(const float* __restrict__ W1) {
    __shared__ float sf[64*102];
    int hc = blockIdx.x;   // 0..7
    int ks = blockIdx.y;   // 0..15
    int hs = threadIdx.x & 31, rg = threadIdx.x >> 5;
    int h = hc*32 + hs;
    float acc[8];
    #pragma unroll
    for (int i = 0; i < 8; i++) acc[i] = 0.f;
    int k0base = ks*KRNG;
    for (int c = 0; c < 4; c++) {
        int k0 = k0base + c*102;
        __syncthreads();
        for (int i = threadIdx.x; i < 64*102; i += 256) {
            int row = i / 102, kk = i % 102;
            sf[i] = d_feat[(size_t)row*FEATK + k0 + kk];
        }
        __syncthreads();
        for (int k = 0; k < 102; k++) {
            float w = W1[(size_t)(k0+k)*PH + h];
            #pragma unroll
            for (int i2 = 0; i2 < 8; i2++)
                acc[i2] += sf[(i2*8+rg)*102 + k] * w;
        }
    }
    #pragma unroll
    for (int i2 = 0; i2 < 8; i2++)
        d_h1p[((size_t)ks*NROW + (i2*8+rg))*PH + h] = acc[i2];
}

__global__ void k_h1post(const float* __restrict__ b1) {
    int i = blockIdx.x*blockDim.x + threadIdx.x;
    if (i >= NROW*PH) return;
    int h = i % PH;
    float s = b1[h];
    #pragma unroll
    for (int ks = 0; ks < KSPL; ks++) s += d_h1p[(size_t)ks*NROW*PH + i];
    d_h1[i] = fmaxf(s, 0.f);
}

// ---------------- K9: h1 @ W2 + b2 ----------------
__global__ void k_gemm2(const float* __restrict__ W2, const float* __restrict__ b2) {
    int row = blockIdx.x;
    __shared__ float sh[PH];
    if (threadIdx.x < PH) sh[threadIdx.x] = d_h1[(size_t)row*PH + threadIdx.x];
    __syncthreads();
    int j = threadIdx.x;
    if (j < 576) {
        float acc = b2[j];
        for (int k = 0; k < PH; k++) acc += sh[k]*W2[(size_t)k*576 + j];
        d_o2[(size_t)row*576 + j] = acc;
    }
}

// ---------------- K10: Wmmse = Cm @ inv(Ar Ar^H + I) ----------------
__global__ void k_wmmse() {
    int bu = blockIdx.x;
    __shared__ float2 Am[144], Cm[144], Rg[12*24], fac[12];
    __shared__ float2 spv;
    __shared__ int piv;
    const float* o = d_o2 + (size_t)bu*576;
    int tid = threadIdx.x;
    if (tid < 144) {
        Cm[tid] = make_float2(o[tid],     o[144+tid]);
        Am[tid] = make_float2(o[288+tid], o[432+tid]);
    }
    __syncthreads();
    if (tid < 144) {
        int i = tid/12, j = tid%12;
        float2 acc = make_float2((i==j)?1.f:0.f, 0.f);
        for (int k = 0; k < 12; k++) {
            float2 x = Am[i*12+k], y = Am[j*12+k];
            acc.x += x.x*y.x + x.y*y.y;
            acc.y += x.y*y.x - x.x*y.y;
        }
        Rg[i*24+j] = acc;
        Rg[i*24+12+j] = make_float2((i==j)?1.f:0.f, 0.f);
    }
    __syncthreads();
    for (int c = 0; c < 12; c++) {
        if (tid == 0) {
            int p = c;
            float2 v0 = Rg[c*24+c];
            float best = v0.x*v0.x + v0.y*v0.y;
            for (int r = c+1; r < 12; r++) {
                float2 v = Rg[r*24+c]; float m = v.x*v.x + v.y*v.y;
                if (m > best) { best = m; p = r; }
            }
            piv = p;
        }
        __syncthreads();
        int p = piv;
        if (p != c && tid < 24) {
            float2 tmp = Rg[c*24+tid]; Rg[c*24+tid] = Rg[p*24+tid]; Rg[p*24+tid] = tmp;
        }
        __syncthreads();
        if (tid == 0) spv = Rg[c*24+c];
        __syncthreads();
        if (tid < 24) {
            float2 pv = spv;
            float den = 1.f/(pv.x*pv.x + pv.y*pv.y);
            float2 inv = make_float2(pv.x*den, -pv.y*den);
            Rg[c*24+tid] = cmul(Rg[c*24+tid], inv);
        }
        __syncthreads();
        if (tid < 12) fac[tid] = Rg[tid*24+c];
        __syncthreads();
        if (tid < 12*24) {
            int r = tid/24, j = tid%24;
            if (r != c) {
                float2 f = fac[r]; float2 pr = Rg[c*24+j];
                float2 v = Rg[r*24+j];
                Rg[r*24+j] = make_float2(v.x - (f.x*pr.x - f.y*pr.y),
                                         v.y - (f.x*pr.y + f.y*pr.x));
            }
        }
        __syncthreads();
    }
    if (tid < 144) {
        int i = tid/12, j = tid%12;
        float2 acc = make_float2(0.f,0.f);
        for (int k = 0; k < 12; k++) {
            float2 x = Cm[i*12+k], y = Rg[k*24+12+j];
            acc.x += x.x*y.x - x.y*y.y;
            acc.y += x.x*y.y + x.y*y.x;
        }
        d_wm[(size_t)bu*144 + tid] = acc;
    }
}

// ---------------- K11: final filter + phasor_T + output ----------------
__global__ void k_final(float* __restrict__ out) {
    int bu = blockIdx.x / PA; int a = blockIdx.x % PA; int b = bu/PUP;
    __shared__ float2 swm[144];
    __shared__ float2 shv[LON];
    __shared__ float  sout[2*PL];
    for (int i = threadIdx.x; i < 144; i += blockDim.x) swm[i] = d_wm[(size_t)bu*144+i];
    for (int i = threadIdx.x; i < LON; i += blockDim.x) shv[i] = d_havg[(size_t)blockIdx.x*LON + i];
    __syncthreads();
    const float2* rs = d_res + (size_t)(b*PA+a)*PL;
    const float2* ph = d_phm + (size_t)bu*PL;
    const float2* pt = d_phT + (size_t)bu*PL;
    for (int jb = threadIdx.x; jb < NB; jb += blockDim.x) {
        float2 hr[12];
        int n0 = jb*12;
        #pragma unroll
        for (int i = 0; i < 12; i++) {
            int n = n0+i;
            float2 h = lerp_havg(shv, n);
            float2 r = rs[n]; float2 p = ph[n];
            hr[i] = make_float2(h.x + r.x*p.x - r.y*p.y,
                                h.y + r.x*p.y + r.y*p.x);
        }
        #pragma unroll
        for (int i = 0; i < 12; i++) {
            float2 acc = make_float2(0.f,0.f);
            #pragma unroll
            for (int j = 0; j < 12; j++) {
                float2 w = swm[i*12+j];
                acc.x += w.x*hr[j].x - w.y*hr[j].y;
                acc.y += w.x*hr[j].y + w.y*hr[j].x;
            }
            int n = n0+i;
            float2 q = pt[n];
            sout[n*2]   = acc.x*q.x + acc.y*q.y;
            sout[n*2+1] = acc.y*q.x - acc.x*q.y;
        }
    }
    __syncthreads();
    float4* dst = (float4*)(out + (size_t)blockIdx.x*2*PL);
    const float4* src = (const float4*)sout;
    for (int i = threadIdx.x; i < (2*PL)/4; i += blockDim.x) dst[i] = src[i];
}

// ---------------- launch ----------------
extern "C" void kernel_launch(void* const* d_in, const int* in_sizes, int n_in,
                              void* d_out, int out_size) {
    const float* lr = (const float*)d_in[0];
    const float* li = (const float*)d_in[1];
    const int*   cs = (const int*)d_in[2];
    const float* W1 = (const float*)d_in[3];
    const float* b1 = (const float*)d_in[4];
    const float* W2 = (const float*)d_in[5];
    const float* b2 = (const float*)d_in[6];
    float* out = (float*)d_out;

    k_tw<<<(PL+255)/256, 256>>>();
    k_stage1<<<PB*PA, 256>>>(lr, li);
    k_peak<<<NROW, 256>>>(cs);
    k_phasor<<<NROW, 256>>>();
    k_havg<<<(NROW*PA*LON+255)/256, 256>>>(lr, li);
    k_resid<<<(PB*PA*PL+255)/256, 256>>>(lr, li);
    k_energyfeat<<<NROW, 1024>>>();
    {
        dim3 g(8, KSPL);
        k_gemm1<<<g, 256>>>(W1);
    }
    k_h1post<<<(NROW*PH+255)/256, 256>>>(b1);
    k_gemm2<<<NROW, 576>>>(W2, b2);
    k_wmmse<<<NROW, 288>>>();
    k_final<<<NROW*PA, 288>>>(out);
}

// round 11
// speedup vs baseline: 1.0994x; 1.0994x over previous
#include <cuda_runtime.h>
#include <math.h>
#include <stdint.h>

#ifndef M_PI
#define M_PI 3.14159265358979323846
#endif

// ---------------- problem constants ----------------
#define PB   8      // B
#define PUP  8      // UP
#define PA   32     // A
#define PL   3264   // L
#define PH   256    // H
#define PBSZ 12
#define PK   12
#define LOCC 4
#define LON  816    // L/LOCC
#define NB   272    // L/BSZ
#define NOFF 61     // DMAX-DMIN+1
#define DMIN (-30)
#define R1   51     // L = 51*64
#define U1   64
#define NROW (PB*PUP)     // 64
#define FEATK (2*PL)      // 6528
#define KSPL 16           // k-splits for gemm1
#define KRNG (FEATK/KSPL) // 408

// ---------------- device scratch (static, no allocs) ----------------
__device__ float2 d_tw[PL];                       // e^{+2pi i r/L}
// ANTENNA-FASTEST layout: d_Y[((b*U1+u)*R1+r)*PA + a]  (coalesced k_peak gather)
__device__ float2 d_Y[PB*U1*R1*PA];
__device__ float  d_m[NROW], d_toff[NROW];
__device__ float2 d_phm[NROW*PL], d_phT[NROW*PL];
__device__ float2 d_havg[NROW*PA*LON];
__device__ float2 d_res[PB*PA*PL];
__device__ float  d_feat[NROW*FEATK];
__device__ float  d_h1p[KSPL*NROW*PH];
__device__ float  d_h1[NROW*PH];
__device__ float  d_o2[NROW*576];
__device__ float2 d_wm[NROW*PBSZ*PBSZ];

// ---------------- helpers ----------------
__device__ __forceinline__ float2 cmul(float2 a, float2 b) {
    return make_float2(a.x*b.x - a.y*b.y, a.x*b.y + a.y*b.x);
}
__device__ __forceinline__ float2 cmulc(float2 a, float2 b) { // a * conj(b)
    return make_float2(a.x*b.x + a.y*b.y, a.y*b.x - a.x*b.y);
}
// jnp.interp replica on a LON-length table (xp = 1.5 + 4j)
__device__ __forceinline__ float2 lerp_havg(const float2* hv, int n) {
    float t = ((float)n - 1.5f) * 0.25f;
    if (t <= 0.f) return hv[0];
    if (t >= (float)(LON-1)) return hv[LON-1];
    int j = (int)t;
    float f = t - (float)j;
    float2 a = hv[j], b = hv[j+1];
    return make_float2(a.x + (b.x-a.x)*f, a.y + (b.y-a.y)*f);
}

// ---------------- K0: twiddles ----------------
__global__ void k_tw() {
    int i = blockIdx.x*blockDim.x + threadIdx.x;
    if (i < PL) {
        double a = 2.0*M_PI*(double)i/(double)PL;
        d_tw[i] = make_float2((float)cos(a), (float)sin(a));
    }
}

// ---------------- K1: partial-DFT stage 1 ----------------
// Y[r,u] = sum_q x[51q+r] e^{2pi i q u /64}, split q = 8q1+q0
__global__ void k_stage1(const float* __restrict__ lr, const float* __restrict__ li) {
    __shared__ float2 z[R1*64];      // Z[(r*8+q0)*8+v]
    __shared__ float2 t64[64];
    int ba = blockIdx.x;
    int b = ba / PA, a = ba % PA;
    const float* rr = lr + (size_t)ba*PL;
    const float* ri = li + (size_t)ba*PL;
    for (int k = threadIdx.x; k < 64; k += blockDim.x) t64[k] = d_tw[k*R1];
    __syncthreads();
    // stage A: 8-point DFT over q1
    for (int o = threadIdx.x; o < R1*64; o += blockDim.x) {
        int v = o & 7, q0 = (o>>3)&7, r = o>>6;
        float2 acc = make_float2(0.f,0.f);
        #pragma unroll
        for (int q1 = 0; q1 < 8; q1++) {
            int id = 51*(8*q1+q0)+r;
            float2 xv = make_float2(rr[id], ri[id]);
            float2 w = t64[8*((q1*v)&7)];
            acc.x += xv.x*w.x - xv.y*w.y;
            acc.y += xv.x*w.y + xv.y*w.x;
        }
        z[(r*8+q0)*8+v] = acc;
    }
    __syncthreads();
    // stage B: combine over q0, write antenna-fastest
    for (int o = threadIdx.x; o < R1*64; o += blockDim.x) {
        int u = o & 63, r = o >> 6, v = u & 7;
        float2 acc = make_float2(0.f,0.f);
        #pragma unroll
        for (int q0 = 0; q0 < 8; q0++) {
            float2 w = t64[(q0*u)&63];
            float2 zv = z[(r*8+q0)*8 + v];
            acc.x += zv.x*w.x - zv.y*w.y;
            acc.y += zv.x*w.y + zv.y*w.x;
        }
        d_Y[(((size_t)b*U1 + u)*R1 + r)*PA + a] = acc;
    }
}

// ---------------- K2: windowed power + argmax -> toff, m ----------------
// Deterministic: one warp per window bin, lane == antenna (coalesced gather
// thanks to antenna-fastest d_Y), fixed-order butterfly reduction.
__global__ void k_peak(const int* __restrict__ shifts) {
    __shared__ float spow[NOFF];
    int b = blockIdx.x / PUP, up = blockIdx.x % PUP;
    int s = shifts[up];
    int peak = ((PK - s) % PK) * (PL / PK);
    int warp = threadIdx.x >> 5;      // 0..7
    int lane = threadIdx.x & 31;      // antenna index
    for (int d = warp; d < NOFF; d += 8) {
        int t = peak + (DMIN + d);
        t %= PL; if (t < 0) t += PL;
        int u = t & 63;
        const float2* Yp = d_Y + (((size_t)b*U1 + u)*R1)*PA + lane;
        float2 acc = make_float2(0.f,0.f);
        int idx = 0;
        for (int r = 0; r < R1; r++) {
            float2 w = d_tw[idx];
            float2 y = Yp[(size_t)r*PA];
            acc.x += y.x*w.x - y.y*w.y;
            acc.y += y.x*w.y + y.y*w.x;
            idx += t; if (idx >= PL) idx -= PL;
        }
        float pw = acc.x*acc.x + acc.y*acc.y;
        #pragma unroll
        for (int off = 16; off > 0; off >>= 1)
            pw += __shfl_xor_sync(0xffffffffu, pw, off);
        if (lane == 0) spow[d] = pw;
    }
    __syncthreads();
    if (threadIdx.x == 0) {
        float vm = spow[0]; int am = 0;
        for (int i = 1; i < NOFF; i++) if (spow[i] > vm) { vm = spow[i]; am = i; }
        float toff = (float)(DMIN + am);
        d_toff[blockIdx.x] = toff;
        d_m[blockIdx.x] = toff + (float)peak;
    }
}

// ---------------- K3: phasor tables (replicate fp32 order of reference) --
// 2D grid: (bu, n-chunk) for full-chip parallelism.
__global__ void k_phasor() {
    int bu = blockIdx.x;
    int n = blockIdx.y*blockDim.x + threadIdx.x;
    if (n >= PL) return;
    const float w = (float)(2.0 * M_PI / (double)PL);
    float wm = w * d_m[bu];
    float wt = w * d_toff[bu];
    float fn = (float)n;
    float am = wm * fn, at = wt * fn;
    float sm_, cm_; sincosf(am, &sm_, &cm_);
    float st_, ct_; sincosf(at, &st_, &ct_);
    d_phm[(size_t)bu*PL+n] = make_float2(cm_, sm_);
    d_phT[(size_t)bu*PL+n] = make_float2(ct_, st_);
}

// ---------------- K4: h_avg = blockmean(ls * phasor_m) ----------------
__global__ void k_havg(const float* __restrict__ lr, const float* __restrict__ li) {
    int idx = blockIdx.x*blockDim.x + threadIdx.x;
    if (idx >= NROW*PA*LON) return;
    int j = idx % LON; int a = (idx / LON) % PA; int bu = idx / (LON*PA);
    int b = bu / PUP;
    const float* rr = lr + (size_t)(b*PA+a)*PL + 4*j;
    const float* ii = li + (size_t)(b*PA+a)*PL + 4*j;
    const float2* ph = d_phm + (size_t)bu*PL + 4*j;
    float2 acc = make_float2(0.f,0.f);
    #pragma unroll
    for (int c = 0; c < 4; c++) {
        float xr = rr[c], xi = ii[c]; float2 p = ph[c];
        acc.x += xr*p.x - xi*p.y;
        acc.y += xr*p.y + xi*p.x;
    }
    d_havg[idx] = make_float2(acc.x*0.25f, acc.y*0.25f);
}

// ---------------- K5: residual = ls - sum_up interp(h_avg)*conj(phm) ----
__global__ void k_resid(const float* __restrict__ lr, const float* __restrict__ li) {
    int idx = blockIdx.x*blockDim.x + threadIdx.x;
    if (idx >= PB*PA*PL) return;
    int n = idx % PL; int a = (idx/PL) % PA; int b = idx/(PL*PA);
    float2 acc = make_float2(0.f,0.f);
    #pragma unroll 1
    for (int up = 0; up < PUP; up++) {
        int bu = b*PUP+up;
        const float2* hv = d_havg + (size_t)(bu*PA+a)*LON;
        float2 h = lerp_havg(hv, n);
        float2 p = d_phm[(size_t)bu*PL+n];
        float2 c = cmulc(h, p);
        acc.x += c.x; acc.y += c.y;
    }
    d_res[idx] = make_float2(lr[idx]-acc.x, li[idx]-acc.y);
}

// ---------------- K6: energies + antenna argmax + MLP features (fused) --
__global__ void k_energyfeat() {
    __shared__ float sen[PA];
    __shared__ int s_a;
    int bu = blockIdx.x; int b = bu/PUP;
    int warp = threadIdx.x >> 5;   // antenna
    int lane = threadIdx.x & 31;
    {
        const float2* hv = d_havg + (size_t)(bu*PA+warp)*LON;
        const float2* rs = d_res + (size_t)(b*PA+warp)*PL;
        const float2* ph = d_phm + (size_t)bu*PL;
        float acc = 0.f;
        for (int n = lane; n < PL; n += 32) {
            float2 h = lerp_havg(hv, n);
            float2 r = rs[n]; float2 p = ph[n];
            float hr = h.x + r.x*p.x - r.y*p.y;
            float hi = h.y + r.x*p.y + r.y*p.x;
            acc += hr*hr + hi*hi;
        }
        #pragma unroll
        for (int off = 16; off > 0; off >>= 1)
            acc += __shfl_xor_sync(0xffffffffu, acc, off);
        if (lane == 0) sen[warp] = acc;
    }
    __syncthreads();
    if (threadIdx.x == 0) {
        float vm = sen[0]; int am = 0;
        for (int i = 1; i < PA; i++) if (sen[i] > vm) { vm = sen[i]; am = i; }
        s_a = am;
    }
    __syncthreads();
    int a = s_a;
    const float2* hv = d_havg + (size_t)(bu*PA+a)*LON;
    const float2* rs = d_res + (size_t)(b*PA+a)*PL;
    const float2* ph = d_phm + (size_t)bu*PL;
    for (int n = threadIdx.x; n < PL; n += blockDim.x) {
        float2 h = lerp_havg(hv, n);
        float2 r = rs[n]; float2 p = ph[n];
        float hr = h.x + r.x*p.x - r.y*p.y;
        float hi = h.y + r.x*p.y + r.y*p.x;
        d_feat[(size_t)bu*FEATK + n]      = hr;
        d_feat[(size_t)bu*FEATK + PL + n] = hi;
    }
}

// ---------------- K8: feat @ W1, split-K deterministic partials ----------
// Inner loop processes k in pairs with float2 LDS (row stride 408 B, 8-B
// aligned) to halve shared-memory wavefronts vs scalar LDS.
__global__ void k_gemm1(const float* __restrict__ W1) {
    __shared__ float sf[64*102];
    int hc = blockIdx.x;   // 0..7
    int ks = blockIdx.y;   // 0..15
    int hs = threadIdx.x & 31, rg = threadIdx.x >> 5;
    int h = hc*32 + hs;
    float acc[8];
    #pragma unroll
    for (int i = 0; i < 8; i++) acc[i] = 0.f;
    int k0base = ks*KRNG;
    for (int c = 0; c < 4; c++) {
        int k0 = k0base + c*102;
        __syncthreads();
        for (int i = threadIdx.x; i < 64*102; i += 256) {
            int row = i / 102, kk = i % 102;
            sf[i] = d_feat[(size_t)row*FEATK + k0 + kk];
        }
        __syncthreads();
        for (int k = 0; k < 102; k += 2) {
            float w0 = W1[(size_t)(k0+k)*PH + h];
            float w1 = W1[(size_t)(k0+k+1)*PH + h];
            #pragma unroll
            for (int i2 = 0; i2 < 8; i2++) {
                float2 fv = *(const float2*)&sf[(i2*8+rg)*102 + k];
                acc[i2] += fv.x * w0;
                acc[i2] += fv.y * w1;
            }
        }
    }
    #pragma unroll
    for (int i2 = 0; i2 < 8; i2++)
        d_h1p[((size_t)ks*NROW + (i2*8+rg))*PH + h] = acc[i2];
}

__global__ void k_h1post(const float* __restrict__ b1) {
    int i = blockIdx.x*blockDim.x + threadIdx.x;
    if (i >= NROW*PH) return;
    int h = i % PH;
    float s = b1[h];
    #pragma unroll
    for (int ks = 0; ks < KSPL; ks++) s += d_h1p[(size_t)ks*NROW*PH + i];
    d_h1[i] = fmaxf(s, 0.f);
}

// ---------------- K9: h1 @ W2 + b2 ----------------
__global__ void k_gemm2(const float* __restrict__ W2, const float* __restrict__ b2) {
    int row = blockIdx.x;
    __shared__ float sh[PH];
    if (threadIdx.x < PH) sh[threadIdx.x] = d_h1[(size_t)row*PH + threadIdx.x];
    __syncthreads();
    int j = threadIdx.x;
    if (j < 576) {
        float acc = b2[j];
        for (int k = 0; k < PH; k++) acc += sh[k]*W2[(size_t)k*576 + j];
        d_o2[(size_t)row*576 + j] = acc;
    }
}

// ---------------- K10: Wmmse = Cm @ inv(Ar Ar^H + I) ----------------
__global__ void k_wmmse() {
    int bu = blockIdx.x;
    __shared__ float2 Am[144], Cm[144], Rg[12*24], fac[12];
    __shared__ float2 spv;
    __shared__ int piv;
    const float* o = d_o2 + (size_t)bu*576;
    int tid = threadIdx.x;
    if (tid < 144) {
        Cm[tid] = make_float2(o[tid],     o[144+tid]);
        Am[tid] = make_float2(o[288+tid], o[432+tid]);
    }
    __syncthreads();
    if (tid < 144) {
        int i = tid/12, j = tid%12;
        float2 acc = make_float2((i==j)?1.f:0.f, 0.f);
        for (int k = 0; k < 12; k++) {
            float2 x = Am[i*12+k], y = Am[j*12+k];
            acc.x += x.x*y.x + x.y*y.y;
            acc.y += x.y*y.x - x.x*y.y;
        }
        Rg[i*24+j] = acc;
        Rg[i*24+12+j] = make_float2((i==j)?1.f:0.f, 0.f);
    }
    __syncthreads();
    for (int c = 0; c < 12; c++) {
        if (tid == 0) {
            int p = c;
            float2 v0 = Rg[c*24+c];
            float best = v0.x*v0.x + v0.y*v0.y;
            for (int r = c+1; r < 12; r++) {
                float2 v = Rg[r*24+c]; float m = v.x*v.x + v.y*v.y;
                if (m > best) { best = m; p = r; }
            }
            piv = p;
        }
        __syncthreads();
        int p = piv;
        if (p != c && tid < 24) {
            float2 tmp = Rg[c*24+tid]; Rg[c*24+tid] = Rg[p*24+tid]; Rg[p*24+tid] = tmp;
        }
        __syncthreads();
        if (tid == 0) spv = Rg[c*24+c];
        __syncthreads();
        if (tid < 24) {
            float2 pv = spv;
            float den = 1.f/(pv.x*pv.x + pv.y*pv.y);
            float2 inv = make_float2(pv.x*den, -pv.y*den);
            Rg[c*24+tid] = cmul(Rg[c*24+tid], inv);
        }
        __syncthreads();
        if (tid < 12) fac[tid] = Rg[tid*24+c];
        __syncthreads();
        if (tid < 12*24) {
            int r = tid/24, j = tid%24;
            if (r != c) {
                float2 f = fac[r]; float2 pr = Rg[c*24+j];
                float2 v = Rg[r*24+j];
                Rg[r*24+j] = make_float2(v.x - (f.x*pr.x - f.y*pr.y),
                                         v.y - (f.x*pr.y + f.y*pr.x));
            }
        }
        __syncthreads();
    }
    if (tid < 144) {
        int i = tid/12, j = tid%12;
        float2 acc = make_float2(0.f,0.f);
        for (int k = 0; k < 12; k++) {
            float2 x = Cm[i*12+k], y = Rg[k*24+12+j];
            acc.x += x.x*y.x - x.y*y.y;
            acc.y += x.x*y.y + x.y*y.x;
        }
        d_wm[(size_t)bu*144 + tid] = acc;
    }
}

// ---------------- K11: final filter + phasor_T + output ----------------
// Two phases: (1) thread<->n coalesced h_res build into smem;
// (2) thread<->n 12x12 matvec from smem, direct coalesced global write.
#define KF_THREADS 544
__global__ void k_final(float* __restrict__ out) {
    int bu = blockIdx.x / PA; int b = bu/PUP;
    int a = blockIdx.x % PA;
    __shared__ float2 swm[144];
    __shared__ float2 shv[LON];
    __shared__ float2 shr[PL];
    for (int i = threadIdx.x; i < 144; i += KF_THREADS) swm[i] = d_wm[(size_t)bu*144+i];
    for (int i = threadIdx.x; i < LON; i += KF_THREADS) shv[i] = d_havg[(size_t)blockIdx.x*LON + i];
    __syncthreads();
    const float2* rs = d_res + (size_t)(b*PA+a)*PL;
    const float2* ph = d_phm + (size_t)bu*PL;
    const float2* pt = d_phT + (size_t)bu*PL;
    // phase 1: h_res
    #pragma unroll
    for (int c = 0; c < PL/KF_THREADS; c++) {
        int n = c*KF_THREADS + threadIdx.x;
        float2 h = lerp_havg(shv, n);
        float2 r = rs[n]; float2 p = ph[n];
        shr[n] = make_float2(h.x + r.x*p.x - r.y*p.y,
                             h.y + r.x*p.y + r.y*p.x);
    }
    __syncthreads();
    // phase 2: per-output-n matvec + phasor_T conj + direct write
    float2* po = (float2*)(out + (size_t)blockIdx.x*2*PL);
    #pragma unroll
    for (int c = 0; c < PL/KF_THREADS; c++) {
        int n = c*KF_THREADS + threadIdx.x;
        int t12 = n/12, i = n - t12*12;
        const float2* hb = &shr[t12*12];
        const float2* wr = &swm[i*12];
        float2 acc = make_float2(0.f,0.f);
        #pragma unroll
        for (int j = 0; j < 12; j++) {
            float2 w = wr[j]; float2 hv = hb[j];
            acc.x += w.x*hv.x - w.y*hv.y;
            acc.y += w.x*hv.y + w.y*hv.x;
        }
        float2 q = pt[n];
        po[n] = make_float2(acc.x*q.x + acc.y*q.y,
                            acc.y*q.x - acc.x*q.y);
    }
}

// ---------------- launch ----------------
extern "C" void kernel_launch(void* const* d_in, const int* in_sizes, int n_in,
                              void* d_out, int out_size) {
    const float* lr = (const float*)d_in[0];
    const float* li = (const float*)d_in[1];
    const int*   cs = (const int*)d_in[2];
    const float* W1 = (const float*)d_in[3];
    const float* b1 = (const float*)d_in[4];
    const float* W2 = (const float*)d_in[5];
    const float* b2 = (const float*)d_in[6];
    float* out = (float*)d_out;

    k_tw<<<(PL+255)/256, 256>>>();
    k_stage1<<<PB*PA, 256>>>(lr, li);
    k_peak<<<NROW, 256>>>(cs);
    {
        dim3 g(NROW, (PL+255)/256);
        k_phasor<<<g, 256>>>();
    }
    k_havg<<<(NROW*PA*LON+255)/256, 256>>>(lr, li);
    k_resid<<<(PB*PA*PL+255)/256, 256>>>(lr, li);
    k_energyfeat<<<NROW, 1024>>>();
    {
        dim3 g(8, KSPL);
        k_gemm1<<<g, 256>>>(W1);
    }
    k_h1post<<<(NROW*PH+255)/256, 256>>>(b1);
    k_gemm2<<<NROW, 576>>>(W2, b2);
    k_wmmse<<<NROW, 288>>>();
    k_final<<<NROW*PA, KF_THREADS>>>(out);
}

// round 15
// speedup vs baseline: 1.2181x; 1.1079x over previous
#include <cuda_runtime.h>
#include <math.h>
#include <stdint.h>

#ifndef M_PI
#define M_PI 3.14159265358979323846
#endif

// ---------------- problem constants ----------------
#define PB   8      // B
#define PUP  8      // UP
#define PA   32     // A
#define PL   3264   // L
#define PH   256    // H
#define PBSZ 12
#define PK   12
#define LOCC 4
#define LON  816    // L/LOCC
#define NB   272    // L/BSZ
#define NOFF 61     // DMAX-DMIN+1
#define DMIN (-30)
#define R1   51     // L = 51*64
#define U1   64
#define NROW (PB*PUP)     // 64
#define FEATK (2*PL)      // 6528
#define KSPL 16           // k-splits for gemm1
#define KRNG (FEATK/KSPL) // 408

// ---------------- device scratch (static, no allocs) ----------------
__device__ float2 d_tw[PL];                       // e^{+2pi i r/L}
// ANTENNA-FASTEST layout: d_Y[((b*U1+u)*R1+r)*PA + a]  (coalesced k_peak gather)
__device__ float2 d_Y[PB*U1*R1*PA];
__device__ float  d_pow_[NROW*NOFF];
__device__ float  d_energy[NROW*PA];
__device__ float  d_m[NROW], d_toff[NROW];
__device__ float2 d_phm[NROW*PL], d_phT[NROW*PL];
__device__ float2 d_havg[NROW*PA*LON];
__device__ float2 d_res[PB*PA*PL];
__device__ float  d_feat[NROW*FEATK];
__device__ float  d_h1p[KSPL*NROW*PH];
__device__ float  d_o2[NROW*576];
__device__ float2 d_wm[NROW*PBSZ*PBSZ];

// ---------------- helpers ----------------
__device__ __forceinline__ float2 cmul(float2 a, float2 b) {
    return make_float2(a.x*b.x - a.y*b.y, a.x*b.y + a.y*b.x);
}
__device__ __forceinline__ float2 cmulc(float2 a, float2 b) { // a * conj(b)
    return make_float2(a.x*b.x + a.y*b.y, a.y*b.x - a.x*b.y);
}
// jnp.interp replica on a LON-length table (xp = 1.5 + 4j)
__device__ __forceinline__ float2 lerp_havg(const float2* hv, int n) {
    float t = ((float)n - 1.5f) * 0.25f;
    if (t <= 0.f) return hv[0];
    if (t >= (float)(LON-1)) return hv[LON-1];
    int j = (int)t;
    float f = t - (float)j;
    float2 a = hv[j], b = hv[j+1];
    return make_float2(a.x + (b.x-a.x)*f, a.y + (b.y-a.y)*f);
}

// ---------------- K0: twiddles (split into 2 launches to aim ncu slot) --
__global__ void k_tw_h(int base) {
    int i = base + blockIdx.x*blockDim.x + threadIdx.x;
    if (i < PL) {
        double a = 2.0*M_PI*(double)i/(double)PL;
        d_tw[i] = make_float2((float)cos(a), (float)sin(a));
    }
}

// ---------------- K1: partial-DFT stage 1 ----------------
// Y[r,u] = sum_q x[51q+r] e^{2pi i q u /64}, split q = 8q1+q0
__global__ void k_stage1(const float* __restrict__ lr, const float* __restrict__ li) {
    __shared__ float2 z[R1*64];      // Z[(r*8+q0)*8+v]
    __shared__ float2 t64[64];
    int ba = blockIdx.x;
    int b = ba / PA, a = ba % PA;
    const float* rr = lr + (size_t)ba*PL;
    const float* ri = li + (size_t)ba*PL;
    for (int k = threadIdx.x; k < 64; k += blockDim.x) t64[k] = d_tw[k*R1];
    __syncthreads();
    // stage A: 8-point DFT over q1
    for (int o = threadIdx.x; o < R1*64; o += blockDim.x) {
        int v = o & 7, q0 = (o>>3)&7, r = o>>6;
        float2 acc = make_float2(0.f,0.f);
        #pragma unroll
        for (int q1 = 0; q1 < 8; q1++) {
            int id = 51*(8*q1+q0)+r;
            float2 xv = make_float2(rr[id], ri[id]);
            float2 w = t64[8*((q1*v)&7)];
            acc.x += xv.x*w.x - xv.y*w.y;
            acc.y += xv.x*w.y + xv.y*w.x;
        }
        z[(r*8+q0)*8+v] = acc;
    }
    __syncthreads();
    // stage B: combine over q0, write antenna-fastest
    for (int o = threadIdx.x; o < R1*64; o += blockDim.x) {
        int u = o & 63, r = o >> 6, v = u & 7;
        float2 acc = make_float2(0.f,0.f);
        #pragma unroll
        for (int q0 = 0; q0 < 8; q0++) {
            float2 w = t64[(q0*u)&63];
            float2 zv = z[(r*8+q0)*8 + v];
            acc.x += zv.x*w.x - zv.y*w.y;
            acc.y += zv.x*w.y + zv.y*w.x;
        }
        d_Y[(((size_t)b*U1 + u)*R1 + r)*PA + a] = acc;
    }
}

// ---------------- K2a: per-(bu,d) windowed power, one warp per bin ------
// grid (NROW, NOFF) x 32 threads: 3904 warps fully hide L2 latency.
// Same summation order + butterfly as before -> bit-identical power.
__global__ void k_peakpow(const int* __restrict__ shifts) {
    int bu = blockIdx.x;
    int b = bu / PUP, up = bu % PUP;
    int d = blockIdx.y;              // 0..NOFF-1
    int lane = threadIdx.x;          // antenna index
    int s = shifts[up];
    int peak = ((PK - s) % PK) * (PL / PK);
    int t = peak + (DMIN + d);
    t %= PL; if (t < 0) t += PL;
    int u = t & 63;
    const float2* Yp = d_Y + (((size_t)b*U1 + u)*R1)*PA + lane;
    float2 acc = make_float2(0.f,0.f);
    int idx = 0;
    for (int r = 0; r < R1; r++) {
        float2 w = d_tw[idx];
        float2 y = Yp[(size_t)r*PA];
        acc.x += y.x*w.x - y.y*w.y;
        acc.y += y.x*w.y + y.y*w.x;
        idx += t; if (idx >= PL) idx -= PL;
    }
    float pw = acc.x*acc.x + acc.y*acc.y;
    #pragma unroll
    for (int off = 16; off > 0; off >>= 1)
        pw += __shfl_xor_sync(0xffffffffu, pw, off);
    if (lane == 0) d_pow_[bu*NOFF + d] = pw;
}

// ---------------- K2b: argmax over bins -> toff, m ----------------
__global__ void k_peakarg(const int* __restrict__ shifts) {
    __shared__ float sp[NOFF];
    int bu = blockIdx.x;
    int up = bu % PUP;
    if (threadIdx.x < NOFF) sp[threadIdx.x] = d_pow_[bu*NOFF + threadIdx.x];
    __syncthreads();
    if (threadIdx.x == 0) {
        float vm = sp[0]; int am = 0;
        for (int i = 1; i < NOFF; i++) if (sp[i] > vm) { vm = sp[i]; am = i; }
        int s = shifts[up];
        int peak = ((PK - s) % PK) * (PL / PK);
        float toff = (float)(DMIN + am);
        d_toff[bu] = toff;
        d_m[bu] = toff + (float)peak;
    }
}

// ---------------- K3: phasor tables (replicate fp32 order of reference) --
__global__ void k_phasor() {
    int bu = blockIdx.x;
    int n = blockIdx.y*blockDim.x + threadIdx.x;
    if (n >= PL) return;
    const float w = (float)(2.0 * M_PI / (double)PL);
    float wm = w * d_m[bu];
    float wt = w * d_toff[bu];
    float fn = (float)n;
    float am = wm * fn, at = wt * fn;
    float sm_, cm_; sincosf(am, &sm_, &cm_);
    float st_, ct_; sincosf(at, &st_, &ct_);
    d_phm[(size_t)bu*PL+n] = make_float2(cm_, sm_);
    d_phT[(size_t)bu*PL+n] = make_float2(ct_, st_);
}

// ---------------- K4: h_avg = blockmean(ls * phasor_m) ----------------
__global__ void k_havg(const float* __restrict__ lr, const float* __restrict__ li) {
    int idx = blockIdx.x*blockDim.x + threadIdx.x;
    if (idx >= NROW*PA*LON) return;
    int j = idx % LON; int a = (idx / LON) % PA; int bu = idx / (LON*PA);
    int b = bu / PUP;
    const float* rr = lr + (size_t)(b*PA+a)*PL + 4*j;
    const float* ii = li + (size_t)(b*PA+a)*PL + 4*j;
    const float2* ph = d_phm + (size_t)bu*PL + 4*j;
    float2 acc = make_float2(0.f,0.f);
    #pragma unroll
    for (int c = 0; c < 4; c++) {
        float xr = rr[c], xi = ii[c]; float2 p = ph[c];
        acc.x += xr*p.x - xi*p.y;
        acc.y += xr*p.y + xi*p.x;
    }
    d_havg[idx] = make_float2(acc.x*0.25f, acc.y*0.25f);
}

// ---------------- K5: residual = ls - sum_up interp(h_avg)*conj(phm) ----
// Fully unrolled up-loop: same add order into acc, much higher MLP.
__global__ void k_resid(const float* __restrict__ lr, const float* __restrict__ li) {
    int idx = blockIdx.x*blockDim.x + threadIdx.x;
    if (idx >= PB*PA*PL) return;
    int n = idx % PL; int a = (idx/PL) % PA; int b = idx/(PL*PA);
    float2 acc = make_float2(0.f,0.f);
    #pragma unroll
    for (int up = 0; up < PUP; up++) {
        int bu = b*PUP+up;
        const float2* hv = d_havg + (size_t)(bu*PA+a)*LON;
        float2 h = lerp_havg(hv, n);
        float2 p = d_phm[(size_t)bu*PL+n];
        float2 c = cmulc(h, p);
        acc.x += c.x; acc.y += c.y;
    }
    d_res[idx] = make_float2(lr[idx]-acc.x, li[idx]-acc.y);
}

// ---------------- K6a: per-antenna energies, grid (NROW, 8) ------------
// warp == antenna within its group of 4; identical reduction as before.
__global__ void k_energy() {
    int bu = blockIdx.x; int b = bu/PUP;
    int warp = threadIdx.x >> 5;   // 0..3
    int lane = threadIdx.x & 31;
    int a = blockIdx.y*4 + warp;   // 0..31
    const float2* hv = d_havg + (size_t)(bu*PA+a)*LON;
    const float2* rs = d_res + (size_t)(b*PA+a)*PL;
    const float2* ph = d_phm + (size_t)bu*PL;
    float acc = 0.f;
    for (int n = lane; n < PL; n += 32) {
        float2 h = lerp_havg(hv, n);
        float2 r = rs[n]; float2 p = ph[n];
        float hr = h.x + r.x*p.x - r.y*p.y;
        float hi = h.y + r.x*p.y + r.y*p.x;
        acc += hr*hr + hi*hi;
    }
    #pragma unroll
    for (int off = 16; off > 0; off >>= 1)
        acc += __shfl_xor_sync(0xffffffffu, acc, off);
    if (lane == 0) d_energy[bu*PA + a] = acc;
}

// ---------------- K6b: antenna argmax + MLP features -------------------
__global__ void k_feat() {
    __shared__ float sen[PA];
    __shared__ int s_a;
    int bu = blockIdx.x; int b = bu/PUP;
    if (threadIdx.x < PA) sen[threadIdx.x] = d_energy[bu*PA + threadIdx.x];
    __syncthreads();
    if (threadIdx.x == 0) {
        float vm = sen[0]; int am = 0;
        for (int i = 1; i < PA; i++) if (sen[i] > vm) { vm = sen[i]; am = i; }
        s_a = am;
    }
    __syncthreads();
    int a = s_a;
    const float2* hv = d_havg + (size_t)(bu*PA+a)*LON;
    const float2* rs = d_res + (size_t)(b*PA+a)*PL;
    const float2* ph = d_phm + (size_t)bu*PL;
    for (int n = threadIdx.x; n < PL; n += blockDim.x) {
        float2 h = lerp_havg(hv, n);
        float2 r = rs[n]; float2 p = ph[n];
        float hr = h.x + r.x*p.x - r.y*p.y;
        float hi = h.y + r.x*p.y + r.y*p.x;
        d_feat[(size_t)bu*FEATK + n]      = hr;
        d_feat[(size_t)bu*FEATK + PL + n] = hi;
    }
}

// ---------------- K8: feat @ W1, split-K deterministic partials ----------
__global__ void k_gemm1(const float* __restrict__ W1) {
    __shared__ float sf[64*102];
    int hc = blockIdx.x;   // 0..7
    int ks = blockIdx.y;   // 0..15
    int hs = threadIdx.x & 31, rg = threadIdx.x >> 5;
    int h = hc*32 + hs;
    float acc[8];
    #pragma unroll
    for (int i = 0; i < 8; i++) acc[i] = 0.f;
    int k0base = ks*KRNG;
    for (int c = 0; c < 4; c++) {
        int k0 = k0base + c*102;
        __syncthreads();
        for (int i = threadIdx.x; i < 64*102; i += 256) {
            int row = i / 102, kk = i % 102;
            sf[i] = d_feat[(size_t)row*FEATK + k0 + kk];
        }
        __syncthreads();
        for (int k = 0; k < 102; k += 2) {
            float w0 = W1[(size_t)(k0+k)*PH + h];
            float w1 = W1[(size_t)(k0+k+1)*PH + h];
            #pragma unroll
            for (int i2 = 0; i2 < 8; i2++) {
                float2 fv = *(const float2*)&sf[(i2*8+rg)*102 + k];
                acc[i2] += fv.x * w0;
                acc[i2] += fv.y * w1;
            }
        }
    }
    #pragma unroll
    for (int i2 = 0; i2 < 8; i2++)
        d_h1p[((size_t)ks*NROW + (i2*8+rg))*PH + h] = acc[i2];
}

// ---------------- K9: (h1post fused) relu(sum partials)+b1, then @W2+b2 -
__global__ void k_gemm2(const float* __restrict__ W2, const float* __restrict__ b2,
                        const float* __restrict__ b1) {
    int row = blockIdx.x;
    __shared__ float sh[PH];
    if (threadIdx.x < PH) {
        float s = b1[threadIdx.x];
        #pragma unroll
        for (int ks = 0; ks < KSPL; ks++)
            s += d_h1p[(size_t)ks*NROW*PH + (size_t)row*PH + threadIdx.x];
        sh[threadIdx.x] = fmaxf(s, 0.f);
    }
    __syncthreads();
    int j = threadIdx.x;
    if (j < 576) {
        float acc = b2[j];
        for (int k = 0; k < PH; k++) acc += sh[k]*W2[(size_t)k*576 + j];
        d_o2[(size_t)row*576 + j] = acc;
    }
}

// ---------------- K10: Wmmse = Cm @ inv(Ar Ar^H + I) ----------------
__global__ void k_wmmse() {
    int bu = blockIdx.x;
    __shared__ float2 Am[144], Cm[144], Rg[12*24], fac[12];
    __shared__ float2 spv;
    __shared__ int piv;
    const float* o = d_o2 + (size_t)bu*576;
    int tid = threadIdx.x;
    if (tid < 144) {
        Cm[tid] = make_float2(o[tid],     o[144+tid]);
        Am[tid] = make_float2(o[288+tid], o[432+tid]);
    }
    __syncthreads();
    if (tid < 144) {
        int i = tid/12, j = tid%12;
        float2 acc = make_float2((i==j)?1.f:0.f, 0.f);
        for (int k = 0; k < 12; k++) {
            float2 x = Am[i*12+k], y = Am[j*12+k];
            acc.x += x.x*y.x + x.y*y.y;
            acc.y += x.y*y.x - x.x*y.y;
        }
        Rg[i*24+j] = acc;
        Rg[i*24+12+j] = make_float2((i==j)?1.f:0.f, 0.f);
    }
    __syncthreads();
    for (int c = 0; c < 12; c++) {
        if (tid == 0) {
            int p = c;
            float2 v0 = Rg[c*24+c];
            float best = v0.x*v0.x + v0.y*v0.y;
            for (int r = c+1; r < 12; r++) {
                float2 v = Rg[r*24+c]; float m = v.x*v.x + v.y*v.y;
                if (m > best) { best = m; p = r; }
            }
            piv = p;
        }
        __syncthreads();
        int p = piv;
        if (p != c && tid < 24) {
            float2 tmp = Rg[c*24+tid]; Rg[c*24+tid] = Rg[p*24+tid]; Rg[p*24+tid] = tmp;
        }
        __syncthreads();
        if (tid == 0) spv = Rg[c*24+c];
        __syncthreads();
        if (tid < 24) {
            float2 pv = spv;
            float den = 1.f/(pv.x*pv.x + pv.y*pv.y);
            float2 inv = make_float2(pv.x*den, -pv.y*den);
            Rg[c*24+tid] = cmul(Rg[c*24+tid], inv);
        }
        __syncthreads();
        if (tid < 12) fac[tid] = Rg[tid*24+c];
        __syncthreads();
        if (tid < 12*24) {
            int r = tid/24, j = tid%24;
            if (r != c) {
                float2 f = fac[r]; float2 pr = Rg[c*24+j];
                float2 v = Rg[r*24+j];
                Rg[r*24+j] = make_float2(v.x - (f.x*pr.x - f.y*pr.y),
                                         v.y - (f.x*pr.y + f.y*pr.x));
            }
        }
        __syncthreads();
    }
    if (tid < 144) {
        int i = tid/12, j = tid%12;
        float2 acc = make_float2(0.f,0.f);
        for (int k = 0; k < 12; k++) {
            float2 x = Cm[i*12+k], y = Rg[k*24+12+j];
            acc.x += x.x*y.x - x.y*y.y;
            acc.y += x.x*y.y + x.y*y.x;
        }
        d_wm[(size_t)bu*144 + tid] = acc;
    }
}

// ---------------- K11: final filter + phasor_T + output ----------------
#define KF_THREADS 544
__global__ void k_final(float* __restrict__ out) {
    int bu = blockIdx.x / PA; int b = bu/PUP;
    int a = blockIdx.x % PA;
    __shared__ float2 swm[144];
    __shared__ float2 shv[LON];
    __shared__ float2 shr[PL];
    for (int i = threadIdx.x; i < 144; i += KF_THREADS) swm[i] = d_wm[(size_t)bu*144+i];
    for (int i = threadIdx.x; i < LON; i += KF_THREADS) shv[i] = d_havg[(size_t)blockIdx.x*LON + i];
    __syncthreads();
    const float2* rs = d_res + (size_t)(b*PA+a)*PL;
    const float2* ph = d_phm + (size_t)bu*PL;
    const float2* pt = d_phT + (size_t)bu*PL;
    // phase 1: h_res
    #pragma unroll
    for (int c = 0; c < PL/KF_THREADS; c++) {
        int n = c*KF_THREADS + threadIdx.x;
        float2 h = lerp_havg(shv, n);
        float2 r = rs[n]; float2 p = ph[n];
        shr[n] = make_float2(h.x + r.x*p.x - r.y*p.y,
                             h.y + r.x*p.y + r.y*p.x);
    }
    __syncthreads();
    // phase 2: per-output-n matvec + phasor_T conj + direct write
    float2* po = (float2*)(out + (size_t)blockIdx.x*2*PL);
    #pragma unroll
    for (int c = 0; c < PL/KF_THREADS; c++) {
        int n = c*KF_THREADS + threadIdx.x;
        int t12 = n/12, i = n - t12*12;
        const float2* hb = &shr[t12*12];
        const float2* wr = &swm[i*12];
        float2 acc = make_float2(0.f,0.f);
        #pragma unroll
        for (int j = 0; j < 12; j++) {
            float2 w = wr[j]; float2 hv = hb[j];
            acc.x += w.x*hv.x - w.y*hv.y;
            acc.y += w.x*hv.y + w.y*hv.x;
        }
        float2 q = pt[n];
        po[n] = make_float2(acc.x*q.x + acc.y*q.y,
                            acc.y*q.x - acc.x*q.y);
    }
}

// ---------------- launch ----------------
extern "C" void kernel_launch(void* const* d_in, const int* in_sizes, int n_in,
                              void* d_out, int out_size) {
    const float* lr = (const float*)d_in[0];
    const float* li = (const float*)d_in[1];
    const int*   cs = (const int*)d_in[2];
    const float* W1 = (const float*)d_in[3];
    const float* b1 = (const float*)d_in[4];
    const float* W2 = (const float*)d_in[5];
    const float* b2 = (const float*)d_in[6];
    float* out = (float*)d_out;

    k_tw_h<<<(PL/2+255)/256, 256>>>(0);          // 1
    k_tw_h<<<(PL/2+255)/256, 256>>>(PL/2);       // 2
    k_stage1<<<PB*PA, 256>>>(lr, li);            // 3
    {
        dim3 g(NROW, NOFF);
        k_peakpow<<<g, 32>>>(cs);                // 4  <- ncu capture slot
    }
    k_peakarg<<<NROW, 64>>>(cs);                 // 5
    {
        dim3 g(NROW, (PL+255)/256);
        k_phasor<<<g, 256>>>();                  // 6
    }
    k_havg<<<(NROW*PA*LON+255)/256, 256>>>(lr, li);   // 7
    k_resid<<<(PB*PA*PL+255)/256, 256>>>(lr, li);     // 8
    {
        dim3 g(NROW, 8);
        k_energy<<<g, 128>>>();                  // 9
    }
    k_feat<<<NROW, 256>>>();                     // 10
    {
        dim3 g(8, KSPL);
        k_gemm1<<<g, 256>>>(W1);                 // 11
    }
    k_gemm2<<<NROW, 576>>>(W2, b2, b1);          // 12
    k_wmmse<<<NROW, 288>>>();                    // 13
    k_final<<<NROW*PA, KF_THREADS>>>(out);       // 14
}